// round 15
// baseline (speedup 1.0000x reference)
#include <cuda_runtime.h>
#include <cuda_bf16.h>
#include <cstdint>

#define BB 8
#define CC 256
#define NN 4096
#define GG 32

#define TQ 128
#define TK 64
#define NIT (NN / TK)

// flash smem (bytes): swizzled, no pads
#define FQ_B   0                 // Q 128 rows x 512 B
#define FK_B   65536             // K 2 bufs x (64 rows x 512 B)
#define FV_B   131072            // V 2 bufs x (256 rows x 128 B)
#define FP_B   196608            // P 2 bufs x (128 rows x 128 B)
#define SMEM_FLASH (229376)

// log2(e)/16 folded into q -> softmax is bare ex2.approx
#define QSCALE 0.0901684403f

__device__ __nv_bfloat16 g_hT[(size_t)BB * NN * CC];
__device__ __nv_bfloat16 g_qkT[(size_t)BB * NN * 512];
__device__ __nv_bfloat16 g_v[(size_t)BB * CC * NN];
__device__ __nv_bfloat16 g_Ob[(size_t)BB * NN * CC];
__device__ __nv_bfloat16 g_wqkv[768 * 256];
__device__ __nv_bfloat16 g_wproj[256 * 256];

// ---------------------------------------------------------------------------
__global__ void cvt_w_kernel(const float* __restrict__ w, __nv_bfloat16* __restrict__ o, int n) {
    int i = blockIdx.x * 256 + threadIdx.x;
    if (i < n) o[i] = __float2bfloat16(w[i]);
}

// ---------------------------------------------------------------------------
// GroupNorm -> hT bf16 [n, c]
// ---------------------------------------------------------------------------
__global__ __launch_bounds__(256) void gn_kernel(const float* __restrict__ x,
                                                 const float* __restrict__ w,
                                                 const float* __restrict__ b,
                                                 __nv_bfloat16* __restrict__ hT) {
    int bg = blockIdx.x;
    int batch = bg >> 5, g = bg & 31;
    size_t base = ((size_t)batch * CC + (size_t)g * 8) * NN;
    const float4* x4 = (const float4*)(x + base);
    int t = threadIdx.x;

    float s = 0.f, ss = 0.f;
    for (int i = t; i < 8192; i += 256) {
        float4 v = x4[i];
        s  += v.x + v.y + v.z + v.w;
        ss += v.x * v.x + v.y * v.y + v.z * v.z + v.w * v.w;
    }
    __shared__ float rs[8], rq[8];
    __shared__ float s_gw[8], s_gb[8];
    __shared__ float st[8][516];
    #pragma unroll
    for (int o = 16; o; o >>= 1) {
        s  += __shfl_xor_sync(0xffffffffu, s, o);
        ss += __shfl_xor_sync(0xffffffffu, ss, o);
    }
    if ((t & 31) == 0) { rs[t >> 5] = s; rq[t >> 5] = ss; }
    __syncthreads();
    if (t == 0) {
        float a = 0.f, c = 0.f;
        #pragma unroll
        for (int i = 0; i < 8; i++) { a += rs[i]; c += rq[i]; }
        rs[0] = a; rq[0] = c;
    }
    __syncthreads();
    float mu  = rs[0] * (1.f / 32768.f);
    float var = rq[0] * (1.f / 32768.f) - mu * mu;
    float rstd = rsqrtf(var + 1e-5f);

    if (t < 8) {
        int c = (g << 3) + t;
        float gwc = w[c] * rstd;
        s_gw[t] = gwc;
        s_gb[t] = b[c] - mu * gwc;
    }
    __syncthreads();

    __nv_bfloat16* ho = hT + (size_t)batch * NN * CC + g * 8;
    for (int chunk = 0; chunk < 8; chunk++) {
        #pragma unroll
        for (int j = 0; j < 4; j++) {
            int f = t + j * 256;
            int c = f >> 7;
            int n4 = f & 127;
            float4 v = x4[c * 1024 + chunk * 128 + n4];
            float gwc = s_gw[c], gbc = s_gb[c];
            st[c][n4 * 4 + 0] = v.x * gwc + gbc;
            st[c][n4 * 4 + 1] = v.y * gwc + gbc;
            st[c][n4 * 4 + 2] = v.z * gwc + gbc;
            st[c][n4 * 4 + 3] = v.w * gwc + gbc;
        }
        __syncthreads();
        #pragma unroll
        for (int j = 0; j < 2; j++) {
            int n = t + j * 256;
            __nv_bfloat162 p0 = __floats2bfloat162_rn(st[0][n], st[1][n]);
            __nv_bfloat162 p1 = __floats2bfloat162_rn(st[2][n], st[3][n]);
            __nv_bfloat162 p2 = __floats2bfloat162_rn(st[4][n], st[5][n]);
            __nv_bfloat162 p3 = __floats2bfloat162_rn(st[6][n], st[7][n]);
            uint4 u;
            u.x = *(uint32_t*)&p0; u.y = *(uint32_t*)&p1;
            u.z = *(uint32_t*)&p2; u.w = *(uint32_t*)&p3;
            *(uint4*)&ho[(size_t)(chunk * 512 + n) * CC] = u;
        }
        __syncthreads();
    }
}

// ---------------------------------------------------------------------------
// helpers
// ---------------------------------------------------------------------------
__device__ __forceinline__ uint32_t s2u(const void* p) {
    return (uint32_t)__cvta_generic_to_shared(p);
}
__device__ __forceinline__ void cp16(void* smem, const void* g) {
    asm volatile("cp.async.cg.shared.global [%0], [%1], 16;\n"
                 :: "r"(s2u(smem)), "l"(g));
}
__device__ __forceinline__ void cp_commit() { asm volatile("cp.async.commit_group;\n"); }
template <int N_>
__device__ __forceinline__ void cp_wait() { asm volatile("cp.async.wait_group %0;\n" :: "n"(N_)); }

__device__ __forceinline__ void ldsm4(uint32_t& r0, uint32_t& r1, uint32_t& r2, uint32_t& r3,
                                      uint32_t addr) {
    asm volatile("ldmatrix.sync.aligned.m8n8.x4.shared.b16 {%0,%1,%2,%3}, [%4];\n"
                 : "=r"(r0), "=r"(r1), "=r"(r2), "=r"(r3) : "r"(addr));
}
__device__ __forceinline__ void mma16816(float* c, const uint32_t* a, const uint32_t* b) {
    asm volatile(
        "mma.sync.aligned.m16n8k16.row.col.f32.bf16.bf16.f32 "
        "{%0,%1,%2,%3}, {%4,%5,%6,%7}, {%8,%9}, {%0,%1,%2,%3};\n"
        : "+f"(c[0]), "+f"(c[1]), "+f"(c[2]), "+f"(c[3])
        : "r"(a[0]), "r"(a[1]), "r"(a[2]), "r"(a[3]), "r"(b[0]), "r"(b[1]));
}
__device__ __forceinline__ uint32_t packbf(float a, float b) {
    __nv_bfloat162 p = __floats2bfloat162_rn(a, b);
    return *(uint32_t*)&p;
}
__device__ __forceinline__ float ex2(float x) {
    float r;
    asm("ex2.approx.f32 %0, %1;" : "=f"(r) : "f"(x));
    return r;
}
// swizzled offsets: 512B-row tiles (Q, K) and 128B-row tiles (V, P)
__device__ __forceinline__ uint32_t sw512(int row, int colbytes) {
    uint32_t chunk = (uint32_t)colbytes >> 4;
    uint32_t sub = (chunk & 7u) ^ ((uint32_t)row & 7u);
    return (uint32_t)row * 512u + (chunk & ~7u) * 16u + sub * 16u + ((uint32_t)colbytes & 15u);
}
__device__ __forceinline__ uint32_t sw128(int row, int colbytes) {
    uint32_t chunk = (uint32_t)colbytes >> 4;
    uint32_t sub = chunk ^ ((uint32_t)row & 7u);
    return (uint32_t)row * 128u + sub * 16u + ((uint32_t)colbytes & 15u);
}

// ---------------------------------------------------------------------------
// bf16 TN MMA GEMM (unchanged from best)
// ---------------------------------------------------------------------------
#define SPITCH 40

template <int OUTMODE>
__global__ __launch_bounds__(256, 2) void mma_gemm(
    const __nv_bfloat16* __restrict__ A, const __nv_bfloat16* __restrict__ B,
    const float* __restrict__ bias, const float* __restrict__ res,
    float* __restrict__ Cf,
    __nv_bfloat16* __restrict__ out_qk, __nv_bfloat16* __restrict__ out_v,
    int M, int N, int K, int lda, int ldb, int ldc,
    long long sA, long long sB, long long sRes, long long sC) {
    __shared__ __nv_bfloat16 sAt[2][128 * SPITCH];
    __shared__ __nv_bfloat16 sBt[2][128 * SPITCH];

    int bz = blockIdx.z;
    A += (size_t)bz * sA;
    B += (size_t)bz * sB;
    if (OUTMODE == 2) { Cf += (size_t)bz * sC; res += (size_t)bz * sRes; }
    else {
        out_qk += (size_t)bz * ((long long)NN * 512);
        out_v  += (size_t)bz * ((long long)CC * NN);
    }

    int m0 = blockIdx.y * 128;
    int n0 = blockIdx.x * 128;
    int t = threadIdx.x;
    int lane = t & 31;
    int wid = t >> 5;
    int wm0 = (wid & 3) * 32;
    int wn0 = (wid >> 2) * 64;

    float acc[2][8][4];
    #pragma unroll
    for (int mi = 0; mi < 2; mi++)
        #pragma unroll
        for (int ni = 0; ni < 8; ni++)
            #pragma unroll
            for (int j = 0; j < 4; j++) acc[mi][ni][j] = 0.f;

    int ktot = K >> 5;
    int lrow0 = t >> 2;
    int lch = (t & 3) * 8;

    {
        #pragma unroll
        for (int p = 0; p < 2; p++) {
            int row = lrow0 + p * 64;
            cp16(&sAt[0][row * SPITCH + lch], A + (size_t)(m0 + row) * lda + lch);
            cp16(&sBt[0][row * SPITCH + lch], B + (size_t)(n0 + row) * ldb + lch);
        }
        cp_commit();
    }

    for (int kt = 0; kt < ktot; kt++) {
        int buf = kt & 1;
        if (kt + 1 < ktot) {
            int nb = buf ^ 1;
            int k0 = (kt + 1) << 5;
            #pragma unroll
            for (int p = 0; p < 2; p++) {
                int row = lrow0 + p * 64;
                cp16(&sAt[nb][row * SPITCH + lch], A + (size_t)(m0 + row) * lda + k0 + lch);
                cp16(&sBt[nb][row * SPITCH + lch], B + (size_t)(n0 + row) * ldb + k0 + lch);
            }
            cp_commit();
            cp_wait<1>();
        } else {
            cp_wait<0>();
        }
        __syncthreads();

        uint32_t baseA = s2u(&sAt[buf][0]);
        uint32_t baseB = s2u(&sBt[buf][0]);
        #pragma unroll
        for (int h = 0; h < 2; h++) {
            int kk = h * 16;
            uint32_t a[2][4];
            #pragma unroll
            for (int mi = 0; mi < 2; mi++) {
                int row = wm0 + mi * 16 + (lane & 15);
                int col = kk + ((lane >> 4) << 3);
                ldsm4(a[mi][0], a[mi][1], a[mi][2], a[mi][3],
                      baseA + (row * SPITCH + col) * 2);
            }
            uint32_t bf[8][2];
            #pragma unroll
            for (int nj = 0; nj < 4; nj++) {
                int seg = lane >> 3, r = lane & 7;
                int n = wn0 + nj * 16 + ((seg >> 1) << 3) + r;
                int col = kk + ((seg & 1) << 3);
                uint32_t r0, r1, r2, r3;
                ldsm4(r0, r1, r2, r3, baseB + (n * SPITCH + col) * 2);
                bf[2 * nj][0] = r0; bf[2 * nj][1] = r1;
                bf[2 * nj + 1][0] = r2; bf[2 * nj + 1][1] = r3;
            }
            #pragma unroll
            for (int mi = 0; mi < 2; mi++)
                #pragma unroll
                for (int ni = 0; ni < 8; ni++)
                    mma16816(acc[mi][ni], a[mi], bf[ni]);
        }
        __syncthreads();
    }

    #pragma unroll
    for (int mi = 0; mi < 2; mi++) {
        int r0 = m0 + wm0 + mi * 16 + (lane >> 2);
        float b0 = bias[r0], b8 = bias[r0 + 8];
        #pragma unroll
        for (int ni = 0; ni < 8; ni++) {
            int c = n0 + wn0 + ni * 8 + 2 * (lane & 3);
            if (OUTMODE == 2) {
                float2 ra = *(const float2*)&res[(size_t)r0 * ldc + c];
                float2 rb = *(const float2*)&res[(size_t)(r0 + 8) * ldc + c];
                float2 v01 = make_float2(acc[mi][ni][0] + b0 + ra.x, acc[mi][ni][1] + b0 + ra.y);
                float2 v23 = make_float2(acc[mi][ni][2] + b8 + rb.x, acc[mi][ni][3] + b8 + rb.y);
                *(float2*)&Cf[(size_t)r0 * ldc + c] = v01;
                *(float2*)&Cf[(size_t)(r0 + 8) * ldc + c] = v23;
            } else {
                float sc = (r0 < 256) ? QSCALE : 1.0f;
                float v0 = (acc[mi][ni][0] + b0) * sc;
                float v1 = (acc[mi][ni][1] + b0) * sc;
                float v2 = (acc[mi][ni][2] + b8) * sc;
                float v3 = (acc[mi][ni][3] + b8) * sc;
                if (r0 < 512) {
                    out_qk[(size_t)c * 512 + r0] = __float2bfloat16(v0);
                    out_qk[(size_t)(c + 1) * 512 + r0] = __float2bfloat16(v1);
                    out_qk[(size_t)c * 512 + r0 + 8] = __float2bfloat16(v2);
                    out_qk[(size_t)(c + 1) * 512 + r0 + 8] = __float2bfloat16(v3);
                } else {
                    *(__nv_bfloat162*)&out_v[(size_t)(r0 - 512) * NN + c] =
                        __floats2bfloat162_rn(v0, v1);
                    *(__nv_bfloat162*)&out_v[(size_t)(r0 - 512 + 8) * NN + c] =
                        __floats2bfloat162_rn(v2, v3);
                }
            }
        }
    }
}

// ---------------------------------------------------------------------------
// Flash attention, role-specialized warps (384 threads / 12 warps):
//   warps 0-3  (S):  S(it) = Q K(it)^T for 32 q-rows each (2 A-frags per K
//                    B-frag -> K read once per 32 rows), exp2 -> P(it) smem.
//   warps 4-11 (PV): O += P(it-1) V(it-1); warp owns 32 q x 128 ch
//                    (2 P A-frags per V B-frag -> V read once per 32 rows).
// Static softmax (q pre-scaled log2e/16), P/K/V double-buffered.
// Per-iter smem traffic 432KB vs 640KB for the uniform-warp version.
// ---------------------------------------------------------------------------
__global__ __launch_bounds__(384, 1) void flash_kernel(
    const __nv_bfloat16* __restrict__ qk,   // [b][n][512]
    const __nv_bfloat16* __restrict__ v,    // [b][c][n]
    __nv_bfloat16* __restrict__ Ob) {       // [b][n][256]
    extern __shared__ char sm[];
    __shared__ float red[128];              // row sums l (tile-local q)

    int batch = blockIdx.y;
    int q0 = blockIdx.x * TQ;
    qk += (size_t)batch * NN * 512;
    v  += (size_t)batch * CC * NN;
    Ob += (size_t)batch * NN * CC;

    int t = threadIdx.x;
    int lane = t & 31;
    int wid = t >> 5;
    int seg = lane >> 3, rr = lane & 7;
    int acolb = (lane >> 4) * 16;

    uint32_t baseQ = s2u(sm + FQ_B);
    uint32_t baseK0 = s2u(sm + FK_B);
    uint32_t baseV0 = s2u(sm + FV_B);
    uint32_t baseP0 = s2u(sm + FP_B);

    // prologue: Q (4096 cp16) + K(0) in group 1; V(0) in group 2
    #pragma unroll
    for (int i = 0; i < 11; i++) {
        int id = t + i * 384;
        if (id < 4096) {
            int row = id >> 5, ch = id & 31;
            cp16(sm + FQ_B + sw512(row, ch * 16), qk + (size_t)(q0 + row) * 512 + ch * 8);
        }
    }
    auto load_k = [&](int it, int kbuf) {
        int kv0 = it * TK;
        #pragma unroll
        for (int i = 0; i < 6; i++) {
            int id = t + i * 384;
            if (id < 2048) {
                int row = id >> 5, ch = id & 31;
                cp16(sm + FK_B + kbuf * 32768 + sw512(row, ch * 16),
                     qk + (size_t)(kv0 + row) * 512 + 256 + ch * 8);
            }
        }
    };
    auto load_v = [&](int it, int vbuf) {
        int kv0 = it * TK;
        #pragma unroll
        for (int i = 0; i < 6; i++) {
            int id = t + i * 384;
            if (id < 2048) {
                int row = id >> 3, ch = id & 7;
                cp16(sm + FV_B + vbuf * 32768 + sw128(row, ch * 16),
                     v + (size_t)row * NN + kv0 + ch * 8);
            }
        }
    };
    load_k(0, 0);
    cp_commit();          // group: Q + K(0)
    load_v(0, 0);
    cp_commit();          // group: V(0)

    // persistent per-role registers
    float oacc[2][16][4];     // PV warps: 32q x 128ch fp32
    float lacc[2][2];         // S warps: partial row sums (4 q rows/thread)
    if (wid >= 4) {
        #pragma unroll
        for (int g = 0; g < 2; g++)
            #pragma unroll
            for (int ni = 0; ni < 16; ni++)
                #pragma unroll
                for (int j = 0; j < 4; j++) oacc[g][ni][j] = 0.f;
    } else {
        lacc[0][0] = lacc[0][1] = lacc[1][0] = lacc[1][1] = 0.f;
    }

    int pw = wid - 4;
    int q0pv = (pw & 3) << 5;          // PV q group (32 rows)
    int ch0 = (pw >> 2) << 7;          // PV channel half (128)

    for (int it = 0; it <= NIT; it++) {
        if (it < NIT) cp_wait<1>();    // K(it) (+older) done; V(it) may be in flight
        else          cp_wait<0>();
        __syncthreads();               // tiles + P(it-1) visible; prev readers done
        if (it + 1 < NIT) {
            load_k(it + 1, (it + 1) & 1);
            cp_commit();
        }

        // ---- S warps: S(it) -> exp2 -> P(it) ----
        if (wid < 4 && it < NIT) {
            uint32_t baseK = baseK0 + (it & 1) * 32768;
            float sacc[2][8][4];
            #pragma unroll
            for (int g = 0; g < 2; g++)
                #pragma unroll
                for (int i = 0; i < 8; i++)
                    #pragma unroll
                    for (int j = 0; j < 4; j++) sacc[g][i][j] = 0.f;

            int arow = (wid << 5) + (lane & 15);
            #pragma unroll
            for (int s = 0; s < 16; s++) {
                uint32_t a0[4], a1[4];
                ldsm4(a0[0], a0[1], a0[2], a0[3], baseQ + sw512(arow, s * 32 + acolb));
                ldsm4(a1[0], a1[1], a1[2], a1[3], baseQ + sw512(arow + 16, s * 32 + acolb));
                #pragma unroll
                for (int nj = 0; nj < 4; nj++) {
                    int n = nj * 16 + ((seg >> 1) << 3) + rr;
                    uint32_t b0, b1, b2, b3;
                    ldsm4(b0, b1, b2, b3, baseK + sw512(n, s * 32 + (seg & 1) * 16));
                    uint32_t bb0[2] = {b0, b1}, bb1[2] = {b2, b3};
                    mma16816(sacc[0][2 * nj], a0, bb0);
                    mma16816(sacc[0][2 * nj + 1], a0, bb1);
                    mma16816(sacc[1][2 * nj], a1, bb0);
                    mma16816(sacc[1][2 * nj + 1], a1, bb1);
                }
            }

            char* pbase = sm + FP_B + (it & 1) * 16384;
            #pragma unroll
            for (int g = 0; g < 2; g++) {
                int qa = (wid << 5) + g * 16 + (lane >> 2);   // tile-local q
                float suma = 0.f, sumb = 0.f;
                #pragma unroll
                for (int n8 = 0; n8 < 8; n8++) {
                    float p0 = ex2(sacc[g][n8][0]);
                    float p1 = ex2(sacc[g][n8][1]);
                    float p2 = ex2(sacc[g][n8][2]);
                    float p3 = ex2(sacc[g][n8][3]);
                    suma += p0 + p1;
                    sumb += p2 + p3;
                    int c = n8 * 8 + 2 * (lane & 3);
                    *(uint32_t*)(pbase + sw128(qa, c * 2)) = packbf(p0, p1);
                    *(uint32_t*)(pbase + sw128(qa + 8, c * 2)) = packbf(p2, p3);
                }
                lacc[g][0] += suma;
                lacc[g][1] += sumb;
            }
        }

        // ---- PV warps: O += P(it-1) V(it-1) ----
        if (wid >= 4 && it > 0) {
            int pb = (it - 1) & 1;
            uint32_t basePr = baseP0 + pb * 16384;
            uint32_t baseVp = baseV0 + pb * 32768;
            #pragma unroll
            for (int j = 0; j < 4; j++) {
                uint32_t pa0[4], pa1[4];
                ldsm4(pa0[0], pa0[1], pa0[2], pa0[3],
                      basePr + sw128(q0pv + (lane & 15), j * 32 + acolb));
                ldsm4(pa1[0], pa1[1], pa1[2], pa1[3],
                      basePr + sw128(q0pv + 16 + (lane & 15), j * 32 + acolb));
                #pragma unroll
                for (int nj = 0; nj < 8; nj++) {
                    int n = ch0 + nj * 16 + ((seg >> 1) << 3) + rr;
                    uint32_t b0, b1, b2, b3;
                    ldsm4(b0, b1, b2, b3, baseVp + sw128(n, j * 32 + (seg & 1) * 16));
                    uint32_t bb0[2] = {b0, b1}, bb1[2] = {b2, b3};
                    mma16816(oacc[0][2 * nj], pa0, bb0);
                    mma16816(oacc[0][2 * nj + 1], pa0, bb1);
                    mma16816(oacc[1][2 * nj], pa1, bb0);
                    mma16816(oacc[1][2 * nj + 1], pa1, bb1);
                }
            }
        }

        // ---- drain iteration: S warps publish row sums ----
        if (wid < 4 && it == NIT) {
            #pragma unroll
            for (int g = 0; g < 2; g++) {
                #pragma unroll
                for (int r = 0; r < 2; r++) {
                    lacc[g][r] += __shfl_xor_sync(0xffffffffu, lacc[g][r], 1);
                    lacc[g][r] += __shfl_xor_sync(0xffffffffu, lacc[g][r], 2);
                }
                if ((lane & 3) == 0) {
                    int qa = (wid << 5) + g * 16 + (lane >> 2);
                    red[qa] = lacc[g][0];
                    red[qa + 8] = lacc[g][1];
                }
            }
        }

        __syncthreads();               // PV done reading V(it-1); P(it) complete; red ready at drain
        if (it + 1 < NIT) {
            load_v(it + 1, (it + 1) & 1);   // into buffer freed by PV(it-1)
            cp_commit();
        }
    }

    // ---- epilogue: normalize + write Ob bf16 [q][c] ----
    if (wid >= 4) {
        #pragma unroll
        for (int g = 0; g < 2; g++) {
            int ql = q0pv + g * 16 + (lane >> 2);
            float ia = 1.f / red[ql];
            float ib = 1.f / red[ql + 8];
            #pragma unroll
            for (int nj = 0; nj < 16; nj++) {
                int c = ch0 + nj * 8 + 2 * (lane & 3);
                *(uint32_t*)&Ob[(size_t)(q0 + ql) * CC + c] =
                    packbf(oacc[g][nj][0] * ia, oacc[g][nj][1] * ia);
                *(uint32_t*)&Ob[(size_t)(q0 + ql + 8) * CC + c] =
                    packbf(oacc[g][nj][2] * ib, oacc[g][nj][3] * ib);
            }
        }
    }
}

// ---------------------------------------------------------------------------
extern "C" void kernel_launch(void* const* d_in, const int* in_sizes, int n_in,
                              void* d_out, int out_size) {
    const float* x  = (const float*)d_in[0];
    const float* nw = (const float*)d_in[1];
    const float* nb = (const float*)d_in[2];
    const float* qw = (const float*)d_in[3];
    const float* qb = (const float*)d_in[4];
    const float* pw = (const float*)d_in[5];
    const float* pb = (const float*)d_in[6];
    float* out = (float*)d_out;

    __nv_bfloat16 *hTP, *qkTP, *vP, *ObP, *wqP, *wpP;
    cudaGetSymbolAddress((void**)&hTP, g_hT);
    cudaGetSymbolAddress((void**)&qkTP, g_qkT);
    cudaGetSymbolAddress((void**)&vP, g_v);
    cudaGetSymbolAddress((void**)&ObP, g_Ob);
    cudaGetSymbolAddress((void**)&wqP, g_wqkv);
    cudaGetSymbolAddress((void**)&wpP, g_wproj);

    const long long sCN = (long long)CC * NN;
    const long long sNC = (long long)NN * CC;

    cudaFuncSetAttribute(flash_kernel, cudaFuncAttributeMaxDynamicSharedMemorySize,
                         SMEM_FLASH);

    cvt_w_kernel<<<768, 256>>>(qw, wqP, 768 * 256);
    cvt_w_kernel<<<256, 256>>>(pw, wpP, 256 * 256);

    gn_kernel<<<BB * GG, 256>>>(x, nw, nb, hTP);

    mma_gemm<1><<<dim3(NN / 128, 768 / 128, BB), 256>>>(
        wqP, hTP, qb, (const float*)0, (float*)0, qkTP, vP,
        768, NN, CC, CC, CC, 0, 0LL, sNC, 0LL, 0LL);

    flash_kernel<<<dim3(NN / TQ, BB), 384, SMEM_FLASH>>>(qkTP, vP, ObP);

    mma_gemm<2><<<dim3(NN / 128, CC / 128, BB), 256>>>(
        wpP, ObP, pb, x, out, (__nv_bfloat16*)0, (__nv_bfloat16*)0,
        CC, NN, CC, CC, CC, NN, 0LL, sNC, sCN, sCN);
}

// round 16
// speedup vs baseline: 1.3249x; 1.3249x over previous
#include <cuda_runtime.h>
#include <cuda_bf16.h>
#include <cstdint>

#define BB 8
#define CC 256
#define NN 4096
#define GG 32

#define TQ 128
#define TK 64
#define QP 264     // 256 + 8 pad
#define VP 72      // 64 + 8 pad
#define NIT (NN / TK)

#define SM_Q   0
#define SM_K   (128 * QP)
#define SM_V   (SM_K + 2 * 64 * QP)
#define SMEM_FLASH ((SM_V + 2 * 256 * VP) * 2)

// log2(e) / 16 : folded into q so flash softmax is a bare ex2.approx
#define QSCALE 0.0901684403f

// Scratch (allocation-free __device__ globals)
__device__ __nv_bfloat16 g_hT[(size_t)BB * NN * CC];
__device__ __nv_bfloat16 g_qkT[(size_t)BB * NN * 512];
__device__ __nv_bfloat16 g_v[(size_t)BB * CC * NN];
__device__ __nv_bfloat16 g_Ob[(size_t)BB * NN * CC];
__device__ __nv_bfloat16 g_wqkv[768 * 256];
__device__ __nv_bfloat16 g_wproj[256 * 256];

// ---------------------------------------------------------------------------
// single fused weight conversion (both weight matrices)
// ---------------------------------------------------------------------------
__global__ void cvt_w_kernel(const float* __restrict__ qw, const float* __restrict__ pw,
                             __nv_bfloat16* __restrict__ oq, __nv_bfloat16* __restrict__ op) {
    int i = blockIdx.x * 256 + threadIdx.x;
    if (i < 768 * 256) oq[i] = __float2bfloat16(qw[i]);
    if (i < 256 * 256) op[i] = __float2bfloat16(pw[i]);
}

// ---------------------------------------------------------------------------
// GroupNorm -> hT bf16 [n, c]. One block per (batch, group).
// ---------------------------------------------------------------------------
__global__ __launch_bounds__(256) void gn_kernel(const float* __restrict__ x,
                                                 const float* __restrict__ w,
                                                 const float* __restrict__ b,
                                                 __nv_bfloat16* __restrict__ hT) {
    int bg = blockIdx.x;
    int batch = bg >> 5, g = bg & 31;
    size_t base = ((size_t)batch * CC + (size_t)g * 8) * NN;
    const float4* x4 = (const float4*)(x + base);
    int t = threadIdx.x;

    float s = 0.f, ss = 0.f;
    for (int i = t; i < 8192; i += 256) {
        float4 v = x4[i];
        s  += v.x + v.y + v.z + v.w;
        ss += v.x * v.x + v.y * v.y + v.z * v.z + v.w * v.w;
    }
    __shared__ float rs[8], rq[8];
    __shared__ float s_gw[8], s_gb[8];
    __shared__ float st[8][516];
    #pragma unroll
    for (int o = 16; o; o >>= 1) {
        s  += __shfl_xor_sync(0xffffffffu, s, o);
        ss += __shfl_xor_sync(0xffffffffu, ss, o);
    }
    if ((t & 31) == 0) { rs[t >> 5] = s; rq[t >> 5] = ss; }
    __syncthreads();
    if (t == 0) {
        float a = 0.f, c = 0.f;
        #pragma unroll
        for (int i = 0; i < 8; i++) { a += rs[i]; c += rq[i]; }
        rs[0] = a; rq[0] = c;
    }
    __syncthreads();
    float mu  = rs[0] * (1.f / 32768.f);
    float var = rq[0] * (1.f / 32768.f) - mu * mu;
    float rstd = rsqrtf(var + 1e-5f);

    if (t < 8) {
        int c = (g << 3) + t;
        float gwc = w[c] * rstd;
        s_gw[t] = gwc;
        s_gb[t] = b[c] - mu * gwc;
    }
    __syncthreads();

    __nv_bfloat16* ho = hT + (size_t)batch * NN * CC + g * 8;
    for (int chunk = 0; chunk < 8; chunk++) {
        #pragma unroll
        for (int j = 0; j < 4; j++) {
            int f = t + j * 256;
            int c = f >> 7;
            int n4 = f & 127;
            float4 v = x4[c * 1024 + chunk * 128 + n4];
            float gwc = s_gw[c], gbc = s_gb[c];
            st[c][n4 * 4 + 0] = v.x * gwc + gbc;
            st[c][n4 * 4 + 1] = v.y * gwc + gbc;
            st[c][n4 * 4 + 2] = v.z * gwc + gbc;
            st[c][n4 * 4 + 3] = v.w * gwc + gbc;
        }
        __syncthreads();
        #pragma unroll
        for (int j = 0; j < 2; j++) {
            int n = t + j * 256;
            __nv_bfloat162 p0 = __floats2bfloat162_rn(st[0][n], st[1][n]);
            __nv_bfloat162 p1 = __floats2bfloat162_rn(st[2][n], st[3][n]);
            __nv_bfloat162 p2 = __floats2bfloat162_rn(st[4][n], st[5][n]);
            __nv_bfloat162 p3 = __floats2bfloat162_rn(st[6][n], st[7][n]);
            uint4 u;
            u.x = *(uint32_t*)&p0; u.y = *(uint32_t*)&p1;
            u.z = *(uint32_t*)&p2; u.w = *(uint32_t*)&p3;
            *(uint4*)&ho[(size_t)(chunk * 512 + n) * CC] = u;
        }
        __syncthreads();
    }
}

// ---------------------------------------------------------------------------
// MMA helpers
// ---------------------------------------------------------------------------
__device__ __forceinline__ uint32_t s2u(const void* p) {
    return (uint32_t)__cvta_generic_to_shared(p);
}
__device__ __forceinline__ void cp16(void* smem, const void* g) {
    asm volatile("cp.async.cg.shared.global [%0], [%1], 16;\n"
                 :: "r"(s2u(smem)), "l"(g));
}
__device__ __forceinline__ void cp_commit() { asm volatile("cp.async.commit_group;\n"); }
template <int N_>
__device__ __forceinline__ void cp_wait() { asm volatile("cp.async.wait_group %0;\n" :: "n"(N_)); }

__device__ __forceinline__ void ldsm4(uint32_t& r0, uint32_t& r1, uint32_t& r2, uint32_t& r3,
                                      uint32_t addr) {
    asm volatile("ldmatrix.sync.aligned.m8n8.x4.shared.b16 {%0,%1,%2,%3}, [%4];\n"
                 : "=r"(r0), "=r"(r1), "=r"(r2), "=r"(r3) : "r"(addr));
}
__device__ __forceinline__ void mma16816(float* c, const uint32_t* a, const uint32_t* b) {
    asm volatile(
        "mma.sync.aligned.m16n8k16.row.col.f32.bf16.bf16.f32 "
        "{%0,%1,%2,%3}, {%4,%5,%6,%7}, {%8,%9}, {%0,%1,%2,%3};\n"
        : "+f"(c[0]), "+f"(c[1]), "+f"(c[2]), "+f"(c[3])
        : "r"(a[0]), "r"(a[1]), "r"(a[2]), "r"(a[3]), "r"(b[0]), "r"(b[1]));
}
__device__ __forceinline__ uint32_t packbf(float a, float b) {
    __nv_bfloat162 p = __floats2bfloat162_rn(a, b);
    return *(uint32_t*)&p;
}
__device__ __forceinline__ float ex2(float x) {
    float r;
    asm("ex2.approx.f32 %0, %1;" : "=f"(r) : "f"(x));
    return r;
}

// ---------------------------------------------------------------------------
// bf16 TN MMA GEMM (128x128 tile, ktile 32, 8 warps, warp 32x64)
// OUTMODE 1: qkv: +bias[m]; m<512 -> qkT[n*512+m] via SMEM-STAGED transpose
//            (coalesced uint4 stores; q rows pre-scaled QSCALE),
//            m>=512 -> v[(m-512)*NN+n]
// OUTMODE 2: proj: Cf[m*ldc+n] = acc + bias[m] + res[m*ldc+n]  (fp32)
// ---------------------------------------------------------------------------
#define SPITCH 40
#define STG_P 136   // staging pitch (bf16 elems): 128 + 8 pad -> conflict-free

template <int OUTMODE>
__global__ __launch_bounds__(256, 2) void mma_gemm(
    const __nv_bfloat16* __restrict__ A, const __nv_bfloat16* __restrict__ B,
    const float* __restrict__ bias, const float* __restrict__ res,
    float* __restrict__ Cf,
    __nv_bfloat16* __restrict__ out_qk, __nv_bfloat16* __restrict__ out_v,
    int M, int N, int K, int lda, int ldb, int ldc,
    long long sA, long long sB, long long sRes, long long sC) {
    // raw smem reused: GEMM double buffers during mainloop, transpose staging
    // in the OUTMODE==1 qk epilogue (mainloop ends with __syncthreads()).
    __shared__ __align__(16) char smem_raw[40960];
    __nv_bfloat16* sAt = (__nv_bfloat16*)smem_raw;                    // [2][128*SPITCH]
    __nv_bfloat16* sBt = sAt + 2 * 128 * SPITCH;                      // [2][128*SPITCH]

    int bz = blockIdx.z;
    A += (size_t)bz * sA;
    B += (size_t)bz * sB;
    if (OUTMODE == 2) { Cf += (size_t)bz * sC; res += (size_t)bz * sRes; }
    else {
        out_qk += (size_t)bz * ((long long)NN * 512);
        out_v  += (size_t)bz * ((long long)CC * NN);
    }

    int m0 = blockIdx.y * 128;
    int n0 = blockIdx.x * 128;
    int t = threadIdx.x;
    int lane = t & 31;
    int wid = t >> 5;
    int wm0 = (wid & 3) * 32;
    int wn0 = (wid >> 2) * 64;

    float acc[2][8][4];
    #pragma unroll
    for (int mi = 0; mi < 2; mi++)
        #pragma unroll
        for (int ni = 0; ni < 8; ni++)
            #pragma unroll
            for (int j = 0; j < 4; j++) acc[mi][ni][j] = 0.f;

    int ktot = K >> 5;
    int lrow0 = t >> 2;
    int lch = (t & 3) * 8;

    {
        #pragma unroll
        for (int p = 0; p < 2; p++) {
            int row = lrow0 + p * 64;
            cp16(&sAt[row * SPITCH + lch], A + (size_t)(m0 + row) * lda + lch);
            cp16(&sBt[row * SPITCH + lch], B + (size_t)(n0 + row) * ldb + lch);
        }
        cp_commit();
    }

    for (int kt = 0; kt < ktot; kt++) {
        int buf = kt & 1;
        if (kt + 1 < ktot) {
            int nb = buf ^ 1;
            int k0 = (kt + 1) << 5;
            #pragma unroll
            for (int p = 0; p < 2; p++) {
                int row = lrow0 + p * 64;
                cp16(&sAt[nb * 128 * SPITCH + row * SPITCH + lch],
                     A + (size_t)(m0 + row) * lda + k0 + lch);
                cp16(&sBt[nb * 128 * SPITCH + row * SPITCH + lch],
                     B + (size_t)(n0 + row) * ldb + k0 + lch);
            }
            cp_commit();
            cp_wait<1>();
        } else {
            cp_wait<0>();
        }
        __syncthreads();

        uint32_t baseA = s2u(&sAt[buf * 128 * SPITCH]);
        uint32_t baseB = s2u(&sBt[buf * 128 * SPITCH]);
        #pragma unroll
        for (int h = 0; h < 2; h++) {
            int kk = h * 16;
            uint32_t a[2][4];
            #pragma unroll
            for (int mi = 0; mi < 2; mi++) {
                int row = wm0 + mi * 16 + (lane & 15);
                int col = kk + ((lane >> 4) << 3);
                ldsm4(a[mi][0], a[mi][1], a[mi][2], a[mi][3],
                      baseA + (row * SPITCH + col) * 2);
            }
            uint32_t bf[8][2];
            #pragma unroll
            for (int nj = 0; nj < 4; nj++) {
                int seg = lane >> 3, r = lane & 7;
                int n = wn0 + nj * 16 + ((seg >> 1) << 3) + r;
                int col = kk + ((seg & 1) << 3);
                uint32_t r0, r1, r2, r3;
                ldsm4(r0, r1, r2, r3, baseB + (n * SPITCH + col) * 2);
                bf[2 * nj][0] = r0; bf[2 * nj][1] = r1;
                bf[2 * nj + 1][0] = r2; bf[2 * nj + 1][1] = r3;
            }
            #pragma unroll
            for (int mi = 0; mi < 2; mi++)
                #pragma unroll
                for (int ni = 0; ni < 8; ni++)
                    mma16816(acc[mi][ni], a[mi], bf[ni]);
        }
        __syncthreads();
    }

    if (OUTMODE == 1 && m0 < 512) {
        // ---- qk epilogue: stage transpose in smem, coalesced 16B stores ----
        __nv_bfloat16* stg = (__nv_bfloat16*)smem_raw;   // [128 tokens][STG_P]
        #pragma unroll
        for (int mi = 0; mi < 2; mi++) {
            int r0 = m0 + wm0 + mi * 16 + (lane >> 2);
            int mloc = wm0 + mi * 16 + (lane >> 2);
            float b0 = bias[r0], b8 = bias[r0 + 8];
            float sc = (r0 < 256) ? QSCALE : 1.0f;
            #pragma unroll
            for (int ni = 0; ni < 8; ni++) {
                int c = wn0 + ni * 8 + 2 * (lane & 3);
                stg[c * STG_P + mloc]           = __float2bfloat16((acc[mi][ni][0] + b0) * sc);
                stg[(c + 1) * STG_P + mloc]     = __float2bfloat16((acc[mi][ni][1] + b0) * sc);
                stg[c * STG_P + mloc + 8]       = __float2bfloat16((acc[mi][ni][2] + b8) * sc);
                stg[(c + 1) * STG_P + mloc + 8] = __float2bfloat16((acc[mi][ni][3] + b8) * sc);
            }
        }
        __syncthreads();
        #pragma unroll
        for (int p = 0; p < 8; p++) {
            int id = t + p * 256;
            int n = id >> 4;               // local token 0..127
            int ch = (id & 15) * 8;        // m chunk (8 bf16 = 16B)
            uint4 u = *(uint4*)&stg[n * STG_P + ch];
            *(uint4*)&out_qk[(size_t)(n0 + n) * 512 + m0 + ch] = u;
        }
        return;
    }

    #pragma unroll
    for (int mi = 0; mi < 2; mi++) {
        int r0 = m0 + wm0 + mi * 16 + (lane >> 2);
        float b0 = bias[r0], b8 = bias[r0 + 8];
        #pragma unroll
        for (int ni = 0; ni < 8; ni++) {
            int c = n0 + wn0 + ni * 8 + 2 * (lane & 3);
            if (OUTMODE == 2) {
                float2 ra = *(const float2*)&res[(size_t)r0 * ldc + c];
                float2 rb = *(const float2*)&res[(size_t)(r0 + 8) * ldc + c];
                float2 v01 = make_float2(acc[mi][ni][0] + b0 + ra.x, acc[mi][ni][1] + b0 + ra.y);
                float2 v23 = make_float2(acc[mi][ni][2] + b8 + rb.x, acc[mi][ni][3] + b8 + rb.y);
                *(float2*)&Cf[(size_t)r0 * ldc + c] = v01;
                *(float2*)&Cf[(size_t)(r0 + 8) * ldc + c] = v23;
            } else {
                // v rows (m0 >= 512): row-major, bf162 stores
                float v0 = acc[mi][ni][0] + b0;
                float v1 = acc[mi][ni][1] + b0;
                float v2 = acc[mi][ni][2] + b8;
                float v3 = acc[mi][ni][3] + b8;
                *(__nv_bfloat162*)&out_v[(size_t)(r0 - 512) * NN + c] =
                    __floats2bfloat162_rn(v0, v1);
                *(__nv_bfloat162*)&out_v[(size_t)(r0 - 512 + 8) * NN + c] =
                    __floats2bfloat162_rn(v2, v3);
            }
        }
    }
}

// ---------------------------------------------------------------------------
// Flash attention (static softmax, exp2): 256 threads / 8 warps, 1 CTA per
// (q-tile 128, batch). Warp handles 16 q-rows. q pre-scaled by log2e/16 so
// P = ex2(S) directly; normalize by row sum in the epilogue.
// ---------------------------------------------------------------------------
__global__ __launch_bounds__(256, 1) void flash_kernel(
    const __nv_bfloat16* __restrict__ qk,   // [b][n][512]
    const __nv_bfloat16* __restrict__ v,    // [b][c][n]
    __nv_bfloat16* __restrict__ Ob) {       // [b][n][256]
    extern __shared__ __nv_bfloat16 sm[];
    __nv_bfloat16* sQ = sm + SM_Q;
    __nv_bfloat16* sK = sm + SM_K;
    __nv_bfloat16* sV = sm + SM_V;

    int batch = blockIdx.y;
    int q0 = blockIdx.x * TQ;
    qk += (size_t)batch * NN * 512;
    v  += (size_t)batch * CC * NN;
    Ob += (size_t)batch * NN * CC;

    int t = threadIdx.x;
    int lane = t & 31;
    int wid = t >> 5;
    int seg = lane >> 3, rr = lane & 7;

    // Load Q tile (128 x 256)
    #pragma unroll
    for (int i = 0; i < 16; i++) {
        int id = t + i * 256;
        int row = id >> 5, c8 = (id & 31) * 8;
        cp16(&sQ[row * QP + c8], qk + (size_t)(q0 + row) * 512 + c8);
    }

    auto load_kv = [&](int it, int buf) {
        int kv0 = it * TK;
        __nv_bfloat16* kb = sK + buf * 64 * QP;
        __nv_bfloat16* vb = sV + buf * 256 * VP;
        #pragma unroll
        for (int i = 0; i < 8; i++) {
            int id = t + i * 256;
            int row = id >> 5, c8 = (id & 31) * 8;
            cp16(&kb[row * QP + c8], qk + (size_t)(kv0 + row) * 512 + 256 + c8);
        }
        #pragma unroll
        for (int i = 0; i < 8; i++) {
            int id = t + i * 256;
            int row = id >> 3, t8 = (id & 7) * 8;
            cp16(&vb[row * VP + t8], v + (size_t)row * NN + kv0 + t8);
        }
    };

    load_kv(0, 0);
    cp_commit();

    float l0 = 0.f, l1 = 0.f;
    float oacc[32][4];
    #pragma unroll
    for (int i = 0; i < 32; i++)
        #pragma unroll
        for (int j = 0; j < 4; j++) oacc[i][j] = 0.f;

    int arow = wid * 16 + (lane & 15);
    int acolo = (lane >> 4) << 3;

    for (int it = 0; it < NIT; it++) {
        int buf = it & 1;
        cp_wait<0>();
        __syncthreads();
        if (it + 1 < NIT) {
            load_kv(it + 1, buf ^ 1);
            cp_commit();
        }

        uint32_t baseQ = s2u(sQ);
        uint32_t baseK = s2u(sK + buf * 64 * QP);
        uint32_t baseV = s2u(sV + buf * 256 * VP);

        // --- S = Q K^T (16 q x 64 kv per warp, k=256) ---
        float sacc[8][4];
        #pragma unroll
        for (int i = 0; i < 8; i++)
            #pragma unroll
            for (int j = 0; j < 4; j++) sacc[i][j] = 0.f;

        #pragma unroll
        for (int k = 0; k < 16; k++) {
            uint32_t a[4];
            ldsm4(a[0], a[1], a[2], a[3], baseQ + (arow * QP + k * 16 + acolo) * 2);
            #pragma unroll
            for (int nj = 0; nj < 4; nj++) {
                int n = nj * 16 + ((seg >> 1) << 3) + rr;
                int col = k * 16 + ((seg & 1) << 3);
                uint32_t b0, b1, b2, b3;
                ldsm4(b0, b1, b2, b3, baseK + (n * QP + col) * 2);
                uint32_t bb0[2] = {b0, b1}, bb1[2] = {b2, b3};
                mma16816(sacc[2 * nj], a, bb0);
                mma16816(sacc[2 * nj + 1], a, bb1);
            }
        }

        // --- static softmax: P = exp2(S), accumulate row sums ---
        float sum0 = 0.f, sum1 = 0.f;
        uint32_t pf[4][4];
        #pragma unroll
        for (int j = 0; j < 4; j++) {
            float p00 = ex2(sacc[2 * j][0]);
            float p01 = ex2(sacc[2 * j][1]);
            float p02 = ex2(sacc[2 * j][2]);
            float p03 = ex2(sacc[2 * j][3]);
            float p10 = ex2(sacc[2 * j + 1][0]);
            float p11 = ex2(sacc[2 * j + 1][1]);
            float p12 = ex2(sacc[2 * j + 1][2]);
            float p13 = ex2(sacc[2 * j + 1][3]);
            sum0 += p00 + p01 + p10 + p11;
            sum1 += p02 + p03 + p12 + p13;
            pf[j][0] = packbf(p00, p01);
            pf[j][1] = packbf(p02, p03);
            pf[j][2] = packbf(p10, p11);
            pf[j][3] = packbf(p12, p13);
        }
        l0 += sum0;
        l1 += sum1;

        // --- O += P V  (k = 64 tokens, n = 256 channels) ---
        #pragma unroll
        for (int j = 0; j < 4; j++) {
            #pragma unroll
            for (int nj = 0; nj < 16; nj++) {
                int n = nj * 16 + ((seg >> 1) << 3) + rr;
                int col = j * 16 + ((seg & 1) << 3);
                uint32_t b0, b1, b2, b3;
                ldsm4(b0, b1, b2, b3, baseV + (n * VP + col) * 2);
                uint32_t bb0[2] = {b0, b1}, bb1[2] = {b2, b3};
                mma16816(oacc[2 * nj], pf[j], bb0);
                mma16816(oacc[2 * nj + 1], pf[j], bb1);
            }
        }
    }

    // row sums across the quad
    l0 += __shfl_xor_sync(0xffffffffu, l0, 1);
    l0 += __shfl_xor_sync(0xffffffffu, l0, 2);
    l1 += __shfl_xor_sync(0xffffffffu, l1, 1);
    l1 += __shfl_xor_sync(0xffffffffu, l1, 2);

    float inv0 = 1.f / l0;
    float inv1 = 1.f / l1;
    int qr = q0 + wid * 16 + (lane >> 2);
    #pragma unroll
    for (int ns = 0; ns < 32; ns++) {
        int c = ns * 8 + 2 * (lane & 3);
        *(__nv_bfloat162*)&Ob[(size_t)qr * CC + c] =
            __floats2bfloat162_rn(oacc[ns][0] * inv0, oacc[ns][1] * inv0);
        *(__nv_bfloat162*)&Ob[(size_t)(qr + 8) * CC + c] =
            __floats2bfloat162_rn(oacc[ns][2] * inv1, oacc[ns][3] * inv1);
    }
}

// ---------------------------------------------------------------------------
extern "C" void kernel_launch(void* const* d_in, const int* in_sizes, int n_in,
                              void* d_out, int out_size) {
    const float* x  = (const float*)d_in[0];
    const float* nw = (const float*)d_in[1];
    const float* nb = (const float*)d_in[2];
    const float* qw = (const float*)d_in[3];
    const float* qb = (const float*)d_in[4];
    const float* pw = (const float*)d_in[5];
    const float* pb = (const float*)d_in[6];
    float* out = (float*)d_out;

    __nv_bfloat16 *hTP, *qkTP, *vP, *ObP, *wqP, *wpP;
    cudaGetSymbolAddress((void**)&hTP, g_hT);
    cudaGetSymbolAddress((void**)&qkTP, g_qkT);
    cudaGetSymbolAddress((void**)&vP, g_v);
    cudaGetSymbolAddress((void**)&ObP, g_Ob);
    cudaGetSymbolAddress((void**)&wqP, g_wqkv);
    cudaGetSymbolAddress((void**)&wpP, g_wproj);

    const long long sCN = (long long)CC * NN;
    const long long sNC = (long long)NN * CC;

    cudaFuncSetAttribute(flash_kernel, cudaFuncAttributeMaxDynamicSharedMemorySize,
                         SMEM_FLASH);

    cvt_w_kernel<<<768, 256>>>(qw, pw, wqP, wpP);

    gn_kernel<<<BB * GG, 256>>>(x, nw, nb, hTP);

    mma_gemm<1><<<dim3(NN / 128, 768 / 128, BB), 256>>>(
        wqP, hTP, qb, (const float*)0, (float*)0, qkTP, vP,
        768, NN, CC, CC, CC, 0, 0LL, sNC, 0LL, 0LL);

    flash_kernel<<<dim3(NN / TQ, BB), 256, SMEM_FLASH>>>(qkTP, vP, ObP);

    mma_gemm<2><<<dim3(NN / 128, CC / 128, BB), 256>>>(
        wpP, ObP, pb, x, out, (__nv_bfloat16*)0, (__nv_bfloat16*)0,
        CC, NN, CC, CC, CC, NN, 0LL, sNC, sCN, sCN);
}